// round 10
// baseline (speedup 1.0000x reference)
#include <cuda_runtime.h>
#include <math.h>

typedef unsigned long long ull;

// Problem dims
constexpr int nB = 128;
constexpr int nS = 128;
constexpr int nV = 128;
constexpr int nH = 512;
constexpr int nL = 64;
constexpr int nG = 3 * nH;     // 1536
constexpr int NBLK = 128;      // persistent scan blocks (<= 148 SMs)

// ---- scratch (device globals; no allocations allowed) ----
__device__ float g_WT[2][nV * nG];            // W_ih transposed [d][v][g]
__device__ float g_xw[2ull * nS * nB * nG];   // [d][s][b][g]
__device__ float g_ys[2ull * nS * nH * nB];   // [d][s][i][b]
// h double buffer, interleaved: [parity][d][k2][b][2]
__device__ float g_h[2][2][nH * nB];
__device__ unsigned g_cnt2[64];               // per-direction arrivals (padded: idx d*32)
__device__ unsigned g_gen2[64];               // per-direction generation (padded)

// ============================================================
// helpers
// ============================================================
__device__ __forceinline__ void fma2(ull& d, ull a, ull b) {
    asm("fma.rn.f32x2 %0, %1, %2, %0;" : "+l"(d) : "l"(a), "l"(b));
}
__device__ __forceinline__ void cpa16(unsigned dst, const void* src) {
    asm volatile("cp.async.cg.shared.global [%0], [%1], 16;" :: "r"(dst), "l"(src));
}
__device__ __forceinline__ void cpa_commit() {
    asm volatile("cp.async.commit_group;");
}
template <int N>
__device__ __forceinline__ void cpa_wait() {
    asm volatile("cp.async.wait_group %0;" :: "n"(N));
}
__device__ __forceinline__ void barh(int id) {   // half-block named barrier
    asm volatile("bar.sync %0, 128;" :: "r"(id) : "memory");
}
__device__ __forceinline__ float sigf(float x) {
    return 1.f / (1.f + expf(-x));
}

// per-direction sense barrier across 128 half-blocks.
// All 128 threads of the half must have fenced before calling.
__device__ __forceinline__ void half_dir_barrier(int d, int tid_h, int barid,
                                                 unsigned target) {
    __threadfence();
    barh(barid);
    if (tid_h == 0) {
        unsigned* cnt = &g_cnt2[d * 32];
        unsigned* gen = &g_gen2[d * 32];
        unsigned t = atomicAdd(cnt, 1);
        if (t == 127) {
            *cnt = 0;
            __threadfence();
            atomicExch(gen, target);
        } else {
            unsigned v;
            do {
                asm volatile("ld.volatile.global.u32 %0, [%1];" : "=r"(v) : "l"(gen));
            } while (v != target);
            __threadfence();
        }
    }
    barh(barid);
}

// ============================================================
// 1) Transpose W_ih (g,v) -> (v,g)
// ============================================================
__global__ void wt_kernel(const float* __restrict__ Wf,
                          const float* __restrict__ Wb) {
    int idx = blockIdx.x * 256 + threadIdx.x;
    if (idx >= 2 * nV * nG) return;
    int d = idx / (nV * nG);
    int rem = idx - d * (nV * nG);
    int v = rem / nG, g = rem - v * nG;
    const float* Wsrc = d ? Wb : Wf;
    g_WT[d][rem] = Wsrc[g * nV + v];
}

// ============================================================
// noop: shifts ncu's profiled launch index onto scan_kernel
// ============================================================
__global__ void noop_kernel() {}

// ============================================================
// 2) Sparse input projection straight from chars (<=16 nnz per row)
// ============================================================
__global__ void __launch_bounds__(256) xwk(const int* __restrict__ chars,
                                           const float* __restrict__ forget,
                                           const float* __restrict__ bihf,
                                           const float* __restrict__ bihb) {
    extern __shared__ float sm[];
    float* Wv  = sm;                       // [128 v][128 g]
    float* swt = sm + 16384;               // [128 b][16]
    int*   sc  = (int*)(sm + 18432);       // [128 b][16]
    float* fp  = sm + 20480;               // forget powers [17]

    int gc = blockIdx.x, s = blockIdx.y, d = blockIdx.z;
    int tid = threadIdx.x;

    const float* WT = g_WT[d];
    for (int p = tid; p < 4096; p += 256) {
        int v = p >> 5, g4 = p & 31;
        *(float4*)&Wv[v * 128 + g4 * 4] =
            *(const float4*)&WT[(size_t)v * nG + gc * 128 + g4 * 4];
    }
    if (tid == 0) {
        float f = *forget;
        fp[0] = 1.f;
        for (int i = 1; i <= 16; i++) fp[i] = fp[i - 1] * f;
    }
    __syncthreads();
    if (tid < 128) {
        int b = tid;
        const int* cp = chars + ((size_t)b * nS + s) * 16;
        int c[16];
#pragma unroll
        for (int w = 0; w < 16; w++) c[w] = cp[w];
        int cnt = 0;
#pragma unroll
        for (int w = 15; w >= 0; w--) {
            bool nz = (c[w] != 0);
            swt[b * 16 + w] = nz ? fp[cnt] : 0.f;
            sc[b * 16 + w] = c[w];
            cnt += nz ? 1 : 0;
        }
    }
    __syncthreads();

    int gq = tid & 31, rp = tid >> 5;
    const float* bih = d ? bihb : bihf;
    float4 bias = *(const float4*)&bih[gc * 128 + gq * 4];
    for (int it = 0; it < 16; it++) {
        int b = it * 8 + rp;
        float a0 = bias.x, a1 = bias.y, a2 = bias.z, a3 = bias.w;
#pragma unroll
        for (int w = 0; w < 16; w++) {
            float ww = swt[b * 16 + w];
            int cc = sc[b * 16 + w];
            float4 wv = *(const float4*)&Wv[cc * 128 + gq * 4];
            a0 += ww * wv.x; a1 += ww * wv.y; a2 += ww * wv.z; a3 += ww * wv.w;
        }
        *(float4*)&g_xw[(((size_t)d * nS + s) * nB + b) * nG + gc * 128 + gq * 4] =
            make_float4(a0, a1, a2, a3);
    }
}

// ============================================================
// 3) Persistent bidirectional GRU scan — BOTH directions per block.
//    128 blocks: i-chunk of 4 (i0 = blk*4), warps 0-3 = forward half,
//    warps 4-7 = backward half. The halves never synchronize with each
//    other: each runs its full 128-step recurrence with its own named
//    barrier + per-direction 128-arrival grid sync. When one half sits
//    in its barrier/L2 latency chain, the other half's warps issue FMA.
//    Half tile: 4 i x 3 gates x 128 b; warp = (ip, bh): 2 i x 3 g x 64 b.
//    Staging: 4 x 16KB buffers (32-k chunks), depth-2, 1 barh per chunk.
// ============================================================
__global__ void __launch_bounds__(256, 1) scan_kernel(
    const float* __restrict__ Whf, const float* __restrict__ bhf,
    const float* __restrict__ Whb, const float* __restrict__ bhb,
    const int* __restrict__ lengths) {
    extern __shared__ float sm[];
    float* Wsm = sm;                     // [2 d][12 rows][512 k] (48 KB)
    float* hst = sm + 12288;             // [2 d][4 buf][16 k2][128 b][2] (128 KB)
    int*   lensm = (int*)(sm + 45056);   // [128]
    unsigned* sbase = (unsigned*)(sm + 45184);  // [2]

    int tid = threadIdx.x;
    int i0 = blockIdx.x * 4;

    // ---- whole-block init ----
    // load W rows for both dirs: row = g*4 + il  (3 gates x 4 i), natural k
    for (int p = tid; p < 3072; p += 256) {
        int dd = p / 1536, rem = p - dd * 1536;
        int row = rem >> 7, q = rem & 127;
        int g = row >> 2, il = row & 3;
        const float* Wsrc = dd ? Whb : Whf;
        float4 v = *(const float4*)&Wsrc[((size_t)g * nH + i0 + il) * nH + q * 4];
        *(float4*)&Wsm[dd * 6144 + row * 512 + q * 4] = v;
    }
    if (tid < 128) lensm[tid] = lengths[tid];
    if (tid == 0 || tid == 128) {
        int dd = tid >> 7;
        unsigned v;
        asm volatile("ld.volatile.global.u32 %0, [%1];" : "=r"(v) : "l"(&g_gen2[dd * 32]));
        sbase[dd] = v;
    }
    // zero initial h (parity 0): per dir 2 k2-rows x 256
    {
        int dd = tid >> 7, j = tid & 127;
        *(float4*)&g_h[0][dd][(size_t)(i0 >> 1) * 256 + j * 4] =
            make_float4(0.f, 0.f, 0.f, 0.f);
    }
    __syncthreads();

    // ---- per-half setup (NO __syncthreads below this point) ----
    int d = tid >> 7;              // direction half
    int tid_h = tid & 127;
    int warp_h = tid_h >> 5, lane = tid & 31;
    int ip = warp_h >> 1;          // i-pair within the 4-i chunk
    int bh = warp_h & 1;           // batch half
    int b0 = bh * 64 + lane * 2;
    int i_a = i0 + ip * 2, i_b = i_a + 1;
    int barid = 1 + d;
    const float* bh_p = d ? bhb : bhf;
    float bR0 = bh_p[i_a], bR1 = bh_p[i_b];
    float bZ0 = bh_p[nH + i_a], bZ1 = bh_p[nH + i_b];
    float bN0 = bh_p[2 * nH + i_a], bN1 = bh_p[2 * nH + i_b];
    float* hd = hst + d * 16384;                     // this dir's 4-buffer ring
    unsigned hd_s = (unsigned)__cvta_generic_to_shared(hd);
    int len0 = lensm[b0], len1 = lensm[b0 + 1];
    unsigned base = sbase[d];

    // weight row base pointers [gate][ii]
    const float* wp[3][2];
#pragma unroll
    for (int g = 0; g < 3; g++)
#pragma unroll
        for (int ii = 0; ii < 2; ii++)
            wp[g][ii] = Wsm + d * 6144 + (g * 4 + ip * 2 + ii) * 512;

    half_dir_barrier(d, tid_h, barid, base + 1);

    for (int step = 0; step < nS; step++) {
        int par = step & 1;
        const float* hin = g_h[par][d];
        float* hout = g_h[par ^ 1][d];

        // --- epilogue inputs: per-thread early LDG (hidden under k-loop) ---
        float2 xg[3][2];
        float4 hold4;
        {
            int lenv[2] = { len0, len1 };
#pragma unroll
            for (int bs = 0; bs < 2; bs++) {
                int b = b0 + bs;
                int len = lenv[bs];
                int seff = d ? ((len - 1 - step) > 0 ? (len - 1 - step) : 0) : step;
                const float* bp = &g_xw[(((size_t)d * nS + seff) * nB + b) * nG + i_a];
                xg[0][bs] = __ldcg((const float2*)bp);
                xg[1][bs] = __ldcg((const float2*)(bp + nH));
                xg[2][bs] = __ldcg((const float2*)(bp + 2 * nH));
            }
            hold4 = __ldcg((const float4*)&hin[(size_t)(i_a >> 1) * 256 + b0 * 2]);
        }

        // --- prologue: stage chunks 0 and 1 (32 k = 4096 floats each) ---
#pragma unroll
        for (int cc = 0; cc < 2; cc++) {
            const float* src = hin + (size_t)cc * 4096;
            unsigned dst = hd_s + (unsigned)(cc * 16384);
#pragma unroll
            for (int q = 0; q < 8; q++) {
                int lin = tid_h + q * 128;
                cpa16(dst + (unsigned)(lin * 16), src + lin * 4);
            }
            cpa_commit();
        }

        // acc[g][ii][bs]: f32x2 (even-k, odd-k) partials
        ull acc[3][2][2];
#pragma unroll
        for (int g = 0; g < 3; g++)
#pragma unroll
            for (int ii = 0; ii < 2; ii++)
#pragma unroll
                for (int bs = 0; bs < 2; bs++) acc[g][ii][bs] = 0ull;

        for (int c = 0; c < 16; c++) {
            if (c < 14) {
                // stage chunk c+2 into buffer (c+2)&3
                const float* src = hin + (size_t)(c + 2) * 4096;
                unsigned dst = hd_s + (unsigned)(((c + 2) & 3) * 16384);
#pragma unroll
                for (int q = 0; q < 8; q++) {
                    int lin = tid_h + q * 128;
                    cpa16(dst + (unsigned)(lin * 16), src + lin * 4);
                }
                cpa_commit();
                cpa_wait<2>();
            } else if (c == 14) {
                cpa_wait<1>();
            } else {
                cpa_wait<0>();
            }
            barh(barid);   // chunk c visible to all half-warps

            const float* hb = hd + (c & 3) * 4096 + b0 * 2;
            const float* pw00 = wp[0][0] + c * 32; const float* pw01 = wp[0][1] + c * 32;
            const float* pw10 = wp[1][0] + c * 32; const float* pw11 = wp[1][1] + c * 32;
            const float* pw20 = wp[2][0] + c * 32; const float* pw21 = wp[2][1] + c * 32;
#pragma unroll
            for (int t = 0; t < 8; t++) {
                ulonglong2 hA = *(const ulonglong2*)(hb + t * 512);        // k2 = 2t
                ulonglong2 hB = *(const ulonglong2*)(hb + t * 512 + 256);  // k2 = 2t+1
                ulonglong2 w0a = *(const ulonglong2*)(pw00 + (t << 2));
                ulonglong2 w0b = *(const ulonglong2*)(pw01 + (t << 2));
                fma2(acc[0][0][0], w0a.x, hA.x); fma2(acc[0][0][0], w0a.y, hB.x);
                fma2(acc[0][0][1], w0a.x, hA.y); fma2(acc[0][0][1], w0a.y, hB.y);
                fma2(acc[0][1][0], w0b.x, hA.x); fma2(acc[0][1][0], w0b.y, hB.x);
                fma2(acc[0][1][1], w0b.x, hA.y); fma2(acc[0][1][1], w0b.y, hB.y);
                ulonglong2 w1a = *(const ulonglong2*)(pw10 + (t << 2));
                ulonglong2 w1b = *(const ulonglong2*)(pw11 + (t << 2));
                fma2(acc[1][0][0], w1a.x, hA.x); fma2(acc[1][0][0], w1a.y, hB.x);
                fma2(acc[1][0][1], w1a.x, hA.y); fma2(acc[1][0][1], w1a.y, hB.y);
                fma2(acc[1][1][0], w1b.x, hA.x); fma2(acc[1][1][0], w1b.y, hB.x);
                fma2(acc[1][1][1], w1b.x, hA.y); fma2(acc[1][1][1], w1b.y, hB.y);
                ulonglong2 w2a = *(const ulonglong2*)(pw20 + (t << 2));
                ulonglong2 w2b = *(const ulonglong2*)(pw21 + (t << 2));
                fma2(acc[2][0][0], w2a.x, hA.x); fma2(acc[2][0][0], w2a.y, hB.x);
                fma2(acc[2][0][1], w2a.x, hA.y); fma2(acc[2][0][1], w2a.y, hB.y);
                fma2(acc[2][1][0], w2b.x, hA.x); fma2(acc[2][1][0], w2b.y, hB.x);
                fma2(acc[2][1][1], w2b.x, hA.y); fma2(acc[2][1][1], w2b.y, hB.y);
            }
        }

        // --- epilogue: fold partials, gates, store h(t+1) + ys ---
        float sG[3][2][2];
#pragma unroll
        for (int g = 0; g < 3; g++)
#pragma unroll
            for (int ii = 0; ii < 2; ii++)
#pragma unroll
                for (int bs = 0; bs < 2; bs++) {
                    float2 a = *(float2*)&acc[g][ii][bs];
                    sG[g][ii][bs] = a.x + a.y;
                }
        float bR[2] = { bR0, bR1 }, bZ[2] = { bZ0, bZ1 }, bN[2] = { bN0, bN1 };
        float holdv[2][2] = { { hold4.x, hold4.z }, { hold4.y, hold4.w } };
        bool msk[2] = { step < len0, step < len1 };
        float ho[2][2], yv[2][2];
#pragma unroll
        for (int ii = 0; ii < 2; ii++) {
#pragma unroll
            for (int bs = 0; bs < 2; bs++) {
                float xr = ii ? xg[0][bs].y : xg[0][bs].x;
                float xz = ii ? xg[1][bs].y : xg[1][bs].x;
                float xn = ii ? xg[2][bs].y : xg[2][bs].x;
                float hold = holdv[ii][bs];
                float rg = sigf(xr + sG[0][ii][bs] + bR[ii]);
                float zg = sigf(xz + sG[1][ii][bs] + bZ[ii]);
                float ng = tanhf(xn + rg * (sG[2][ii][bs] + bN[ii]));
                float hn = (1.f - zg) * ng + zg * hold;
                ho[ii][bs] = msk[bs] ? hn : hold;
                yv[ii][bs] = msk[bs] ? hn : 0.f;
            }
        }
        *(float4*)&hout[(size_t)(i_a >> 1) * 256 + b0 * 2] =
            make_float4(ho[0][0], ho[1][0], ho[0][1], ho[1][1]);
#pragma unroll
        for (int ii = 0; ii < 2; ii++)
            *(float2*)&g_ys[(((size_t)d * nS + step) * nH + i_a + ii) * nB + b0] =
                make_float2(yv[ii][0], yv[ii][1]);

        half_dir_barrier(d, tid_h, barid, base + 2 + step);
    }
}

// ============================================================
// 4) Output head (unchanged)
// ============================================================
__global__ void __launch_bounds__(256) out_kernel(
    const float* __restrict__ Wlin, const float* __restrict__ blin,
    const int* __restrict__ lengths, float* __restrict__ out) {
    __shared__ float As[64][64];
    __shared__ float Ws[64][65];
    __shared__ int lensm[64];
    int bh = blockIdx.x, s = blockIdx.y;
    int tid = threadIdx.x;
    if (tid < 64) lensm[tid] = lengths[bh * 64 + tid];
    int l = tid & 63, bg = tid >> 6;
    float acc[16];
#pragma unroll
    for (int j = 0; j < 16; j++) acc[j] = 0.f;

    for (int kc = 0; kc < 1024; kc += 64) {
        __syncthreads();
        if (kc < 512) {
            for (int p = tid; p < 1024; p += 256) {
                int kk = p >> 4, b4 = (p & 15) * 4;
                *(float4*)&As[kk][b4] = *(const float4*)
                    &g_ys[(((size_t)0 * nS + s) * nH + kc + kk) * nB + bh * 64 + b4];
            }
        } else {
            for (int p = tid; p < 4096; p += 256) {
                int kk = p >> 6, bb = p & 63;
                int b = bh * 64 + bb, len = lensm[bb];
                float v = 0.f;
                if (s < len) {
                    int t = len - 1 - s;
                    v = g_ys[(((size_t)1 * nS + t) * nH + (kc - 512 + kk)) * nB + b];
                }
                As[kk][bb] = v;
            }
        }
        for (int p = tid; p < 1024; p += 256) {
            int ll = p >> 4, k = (p & 15) * 4;
            float4 v = *(const float4*)&Wlin[(size_t)ll * 1024 + kc + k];
            Ws[k + 0][ll] = v.x; Ws[k + 1][ll] = v.y;
            Ws[k + 2][ll] = v.z; Ws[k + 3][ll] = v.w;
        }
        __syncthreads();
#pragma unroll 8
        for (int kk = 0; kk < 64; kk++) {
            float wv = Ws[kk][l];
            float4 h0 = *(float4*)&As[kk][bg * 16 + 0];
            float4 h1 = *(float4*)&As[kk][bg * 16 + 4];
            float4 h2 = *(float4*)&As[kk][bg * 16 + 8];
            float4 h3 = *(float4*)&As[kk][bg * 16 + 12];
            acc[0] += h0.x * wv; acc[1] += h0.y * wv; acc[2] += h0.z * wv; acc[3] += h0.w * wv;
            acc[4] += h1.x * wv; acc[5] += h1.y * wv; acc[6] += h1.z * wv; acc[7] += h1.w * wv;
            acc[8] += h2.x * wv; acc[9] += h2.y * wv; acc[10] += h2.z * wv; acc[11] += h2.w * wv;
            acc[12] += h3.x * wv; acc[13] += h3.y * wv; acc[14] += h3.z * wv; acc[15] += h3.w * wv;
        }
    }
    __syncthreads();
    float bias = blin[l];
#pragma unroll
    for (int j = 0; j < 16; j++) As[bg * 16 + j][l] = acc[j] + bias;
    __syncthreads();
    for (int p = tid; p < 1024; p += 256) {
        int bb = p >> 4, l4 = (p & 15) * 4;
        *(float4*)&out[(size_t)(bh * 64 + bb) * nS * nL + s * nL + l4] =
            *(float4*)&As[bb][l4];
    }
}

// ============================================================
extern "C" void kernel_launch(void* const* d_in, const int* in_sizes, int n_in,
                              void* d_out, int out_size) {
    const int*   chars   = (const int*)d_in[0];
    const int*   lengths = (const int*)d_in[1];
    const float* forget  = (const float*)d_in[2];
    const float* W_ih_f  = (const float*)d_in[3];
    const float* W_hh_f  = (const float*)d_in[4];
    const float* b_ih_f  = (const float*)d_in[5];
    const float* b_hh_f  = (const float*)d_in[6];
    const float* W_ih_b  = (const float*)d_in[7];
    const float* W_hh_b  = (const float*)d_in[8];
    const float* b_ih_b  = (const float*)d_in[9];
    const float* b_hh_b  = (const float*)d_in[10];
    const float* W_lin   = (const float*)d_in[11];
    const float* b_lin   = (const float*)d_in[12];
    float* out = (float*)d_out;

    cudaFuncSetAttribute(xwk, cudaFuncAttributeMaxDynamicSharedMemorySize, 90 * 1024);
    cudaFuncSetAttribute(scan_kernel, cudaFuncAttributeMaxDynamicSharedMemorySize, 184 * 1024);

    wt_kernel<<<(2 * nV * nG + 255) / 256, 256>>>(W_ih_f, W_ih_b);
    xwk<<<dim3(12, 128, 2), 256, 82000>>>(chars, forget, b_ih_f, b_ih_b);
    noop_kernel<<<1, 32>>>();   // shifts ncu capture slot onto scan_kernel
    scan_kernel<<<NBLK, 256, 181000>>>(W_hh_f, b_hh_f, W_hh_b, b_hh_b, lengths);
    out_kernel<<<dim3(2, 128), 256>>>(W_lin, b_lin, lengths, out);
}

// round 11
// speedup vs baseline: 1.0531x; 1.0531x over previous
#include <cuda_runtime.h>
#include <math.h>

typedef unsigned long long ull;

// Problem dims
constexpr int nB = 128;
constexpr int nS = 128;
constexpr int nV = 128;
constexpr int nH = 512;
constexpr int nL = 64;
constexpr int nG = 3 * nH;     // 1536
constexpr int NBLK = 128;      // persistent scan blocks (<= 148 SMs)

// ---- scratch (device globals; no allocations allowed) ----
__device__ float g_WT[2][nV * nG];            // W_ih transposed [d][v][g]
__device__ float g_xw[2ull * nS * nB * nG];   // [d][s][b][g]
__device__ float g_ys[2ull * nS * nH * nB];   // [d][s][i][b]
// h double buffer, interleaved: [parity][d][k2][b][2]
__device__ float g_h[2][2][nH * nB];
__device__ unsigned g_cnt2[64];               // per-direction arrivals (idx d*32)
__device__ unsigned g_gen2[64];               // per-direction generation (idx d*32)

// ============================================================
// helpers
// ============================================================
__device__ __forceinline__ void fma2(ull& d, ull a, ull b) {
    asm("fma.rn.f32x2 %0, %1, %2, %0;" : "+l"(d) : "l"(a), "l"(b));
}
__device__ __forceinline__ void bulkcp(unsigned dst, const void* src,
                                       unsigned bytes, unsigned mbar) {
    asm volatile(
        "cp.async.bulk.shared::cta.global.mbarrier::complete_tx::bytes [%0], [%1], %2, [%3];"
        :: "r"(dst), "l"(src), "r"(bytes), "r"(mbar) : "memory");
}
__device__ __forceinline__ void mb_init(unsigned a) {
    asm volatile("mbarrier.init.shared.b64 [%0], 1;" :: "r"(a) : "memory");
}
__device__ __forceinline__ void mb_inval(unsigned a) {
    asm volatile("mbarrier.inval.shared.b64 [%0];" :: "r"(a) : "memory");
}
__device__ __forceinline__ void mb_tx(unsigned a, unsigned bytes) {
    asm volatile("mbarrier.arrive.expect_tx.shared.b64 _, [%0], %1;"
                 :: "r"(a), "r"(bytes) : "memory");
}
__device__ __forceinline__ void mb_wait0(unsigned a) {   // parity 0 (fresh init)
    unsigned done;
    do {
        asm volatile(
            "{\n\t.reg .pred p;\n\t"
            "mbarrier.try_wait.parity.acquire.cta.shared::cta.b64 p, [%1], 0, 0x989680;\n\t"
            "selp.b32 %0, 1, 0, p;\n\t}"
            : "=r"(done) : "r"(a) : "memory");
    } while (!done);
}
__device__ __forceinline__ float sigf(float x) {
    return 1.f / (1.f + expf(-x));
}

// per-direction sense barrier across 64 co-resident blocks
__device__ __forceinline__ void dir_barrier(int d, unsigned target) {
    __threadfence();
    __syncthreads();
    if (threadIdx.x == 0) {
        unsigned* cnt = &g_cnt2[d * 32];
        unsigned* gen = &g_gen2[d * 32];
        unsigned t = atomicAdd(cnt, 1);
        if (t == 63) {
            *cnt = 0;
            __threadfence();
            atomicExch(gen, target);
        } else {
            unsigned v;
            do {
                asm volatile("ld.volatile.global.u32 %0, [%1];" : "=r"(v) : "l"(gen));
            } while (v != target);
            __threadfence();
        }
    }
    __syncthreads();
}

// ============================================================
// 1) Transpose W_ih (g,v) -> (v,g)
// ============================================================
__global__ void wt_kernel(const float* __restrict__ Wf,
                          const float* __restrict__ Wb) {
    int idx = blockIdx.x * 256 + threadIdx.x;
    if (idx >= 2 * nV * nG) return;
    int d = idx / (nV * nG);
    int rem = idx - d * (nV * nG);
    int v = rem / nG, g = rem - v * nG;
    const float* Wsrc = d ? Wb : Wf;
    g_WT[d][rem] = Wsrc[g * nV + v];
}

// ============================================================
// noop: keeps ncu's profiled launch slot on scan_kernel
// ============================================================
__global__ void noop_kernel() {}

// ============================================================
// 2) Sparse input projection straight from chars (<=16 nnz per row)
// ============================================================
__global__ void __launch_bounds__(256) xwk(const int* __restrict__ chars,
                                           const float* __restrict__ forget,
                                           const float* __restrict__ bihf,
                                           const float* __restrict__ bihb) {
    extern __shared__ float sm[];
    float* Wv  = sm;                       // [128 v][128 g]
    float* swt = sm + 16384;               // [128 b][16]
    int*   sc  = (int*)(sm + 18432);       // [128 b][16]
    float* fp  = sm + 20480;               // forget powers [17]

    int gc = blockIdx.x, s = blockIdx.y, d = blockIdx.z;
    int tid = threadIdx.x;

    const float* WT = g_WT[d];
    for (int p = tid; p < 4096; p += 256) {
        int v = p >> 5, g4 = p & 31;
        *(float4*)&Wv[v * 128 + g4 * 4] =
            *(const float4*)&WT[(size_t)v * nG + gc * 128 + g4 * 4];
    }
    if (tid == 0) {
        float f = *forget;
        fp[0] = 1.f;
        for (int i = 1; i <= 16; i++) fp[i] = fp[i - 1] * f;
    }
    __syncthreads();
    if (tid < 128) {
        int b = tid;
        const int* cp = chars + ((size_t)b * nS + s) * 16;
        int c[16];
#pragma unroll
        for (int w = 0; w < 16; w++) c[w] = cp[w];
        int cnt = 0;
#pragma unroll
        for (int w = 15; w >= 0; w--) {
            bool nz = (c[w] != 0);
            swt[b * 16 + w] = nz ? fp[cnt] : 0.f;
            sc[b * 16 + w] = c[w];
            cnt += nz ? 1 : 0;
        }
    }
    __syncthreads();

    int gq = tid & 31, rp = tid >> 5;
    const float* bih = d ? bihb : bihf;
    float4 bias = *(const float4*)&bih[gc * 128 + gq * 4];
    for (int it = 0; it < 16; it++) {
        int b = it * 8 + rp;
        float a0 = bias.x, a1 = bias.y, a2 = bias.z, a3 = bias.w;
#pragma unroll
        for (int w = 0; w < 16; w++) {
            float ww = swt[b * 16 + w];
            int cc = sc[b * 16 + w];
            float4 wv = *(const float4*)&Wv[cc * 128 + gq * 4];
            a0 += ww * wv.x; a1 += ww * wv.y; a2 += ww * wv.z; a3 += ww * wv.w;
        }
        *(float4*)&g_xw[(((size_t)d * nS + s) * nB + b) * nG + gc * 128 + gq * 4] =
            make_float4(a0, a1, a2, a3);
    }
}

// ============================================================
// 3) Persistent bidirectional GRU scan — bulk-copy staging + rotated
//    chunk order. 128 blocks: d = blk>>6, i-chunk of 8 = blk&63.
//    Warp w: row pair r0=2*(w&3), batch half (w>>2), 2 batches/lane.
//    h staged per chunk as ONE cp.async.bulk (32 KB) into a 3-buffer
//    ring, completion via per-chunk mbarrier (fresh-init per step,
//    parity always 0). Chunk sequence rotated by ic to spread L2 load.
// ============================================================
__global__ void __launch_bounds__(256, 1) scan_kernel(
    const float* __restrict__ Whf, const float* __restrict__ bhf,
    const float* __restrict__ Whb, const float* __restrict__ bhb,
    const int* __restrict__ lengths) {
    extern __shared__ float sm[];
    float* Wsm = sm;                     // [24 rows][512 k] (48 KB)
    float* hst = sm + 12288;             // 3 x [32 k2][128 b][2] (96 KB)
    int*   lensm = (int*)(sm + 36864);   // [128]
    unsigned* sbase = (unsigned*)(sm + 36992);
    // 8 mbarriers, 8B-aligned (float idx 37004 -> byte 148016, %8==0)
    unsigned mb_base_idx = 37004;

    int tid = threadIdx.x;
    int d = blockIdx.x >> 6, ic = blockIdx.x & 63, i0 = ic * 8;
    const float* Wh = d ? Whb : Whf;
    const float* bh_p = d ? bhb : bhf;

    unsigned smem0 = (unsigned)__cvta_generic_to_shared(sm);
    unsigned hst_s = smem0 + 12288u * 4u;
    unsigned mb0 = smem0 + mb_base_idx * 4u;

    // load 24 W rows (3 gates x 8 i) once, natural layout
    for (int p = tid; p < 3072; p += 256) {
        int row = p >> 7, q = p & 127;
        float4 v = *(const float4*)&Wh[((size_t)(row >> 3) * nH + i0 + (row & 7)) * nH + q * 4];
        *(float4*)&Wsm[row * 512 + q * 4] = v;
    }
    if (tid < 128) lensm[tid] = lengths[tid];
    if (tid == 0) {
        unsigned v;
        asm volatile("ld.volatile.global.u32 %0, [%1];" : "=r"(v) : "l"(&g_gen2[d * 32]));
        *sbase = v;
    }
    // init the 8 per-chunk mbarriers for step 0
    if (tid < 8) mb_init(mb0 + tid * 8);
    // zero initial hidden state (parity 0), this block's k2 slice
    for (int p = tid; p < 1024; p += 256)
        g_h[0][d][(size_t)(i0 >> 1) * 256 + p] = 0.f;
    __syncthreads();
    unsigned base = *sbase;
    dir_barrier(d, base + 1);

    int w = tid >> 5, lane = tid & 31;
    int r0 = (w & 3) * 2;
    int b0 = ((w & 4) << 4) + lane * 2;   // (w>>2)*64 + lane*2
    int i_a = i0 + r0, i_b = i_a + 1;
    float bR0 = bh_p[i_a], bR1 = bh_p[i_b];
    float bZ0 = bh_p[nH + i_a], bZ1 = bh_p[nH + i_b];
    float bN0 = bh_p[2 * nH + i_a], bN1 = bh_p[2 * nH + i_b];
    int len0 = lensm[b0], len1 = lensm[b0 + 1];

    // per-warp weight row base pointers [gate][ii]
    const float* wp[3][2];
#pragma unroll
    for (int g = 0; g < 3; g++)
#pragma unroll
        for (int ii = 0; ii < 2; ii++)
            wp[g][ii] = Wsm + ((g * 8 + r0 + ii) << 9);

    for (int step = 0; step < nS; step++) {
        int par = step & 1;
        const float* hin = g_h[par][d];
        float* hout = g_h[par ^ 1][d];

        // --- epilogue inputs: per-thread early LDG (hidden under k-loop) ---
        float2 xg[3][2];
        float4 hold4;
        {
            int lenv[2] = { len0, len1 };
#pragma unroll
            for (int bs = 0; bs < 2; bs++) {
                int b = b0 + bs;
                int len = lenv[bs];
                int seff = d ? ((len - 1 - step) > 0 ? (len - 1 - step) : 0) : step;
                const float* bp = &g_xw[(((size_t)d * nS + seff) * nB + b) * nG + i_a];
                xg[0][bs] = __ldcg((const float2*)bp);
                xg[1][bs] = __ldcg((const float2*)(bp + nH));
                xg[2][bs] = __ldcg((const float2*)(bp + 2 * nH));
            }
            hold4 = __ldcg((const float4*)&hin[(size_t)(i_a >> 1) * 256 + b0 * 2]);
        }

        // --- prologue: issue bulk copies for sequence slots 0..2 ---
        if (tid == 0) {
#pragma unroll
            for (int jj = 0; jj < 3; jj++) {
                int cs = (jj + ic) & 7;
                mb_tx(mb0 + jj * 8, 32768u);
                bulkcp(hst_s + (unsigned)(jj * 32768), hin + (size_t)cs * 8192,
                       32768u, mb0 + jj * 8);
            }
        }

        // acc[g][ii][bs]: f32x2 (even-k, odd-k) partials
        ull acc[3][2][2];
#pragma unroll
        for (int g = 0; g < 3; g++)
#pragma unroll
            for (int ii = 0; ii < 2; ii++)
#pragma unroll
                for (int bs = 0; bs < 2; bs++) acc[g][ii][bs] = 0ull;

        for (int j = 0; j < 8; j++) {
            int cs = (j + ic) & 7;
            mb_wait0(mb0 + (unsigned)(j * 8));   // chunk seq j staged

            const float* hb = hst + (j % 3) * 8192 + (b0 << 1);
            int co = cs << 6;
            const float* pw00 = wp[0][0] + co; const float* pw01 = wp[0][1] + co;
            const float* pw10 = wp[1][0] + co; const float* pw11 = wp[1][1] + co;
            const float* pw20 = wp[2][0] + co; const float* pw21 = wp[2][1] + co;
#pragma unroll
            for (int t = 0; t < 16; t++) {
                ulonglong2 hA = *(const ulonglong2*)(hb + (t << 9));        // k2=2t
                ulonglong2 hB = *(const ulonglong2*)(hb + (t << 9) + 256);  // k2=2t+1
                ulonglong2 w0a = *(const ulonglong2*)(pw00 + (t << 2));
                ulonglong2 w0b = *(const ulonglong2*)(pw01 + (t << 2));
                fma2(acc[0][0][0], w0a.x, hA.x); fma2(acc[0][0][0], w0a.y, hB.x);
                fma2(acc[0][0][1], w0a.x, hA.y); fma2(acc[0][0][1], w0a.y, hB.y);
                fma2(acc[0][1][0], w0b.x, hA.x); fma2(acc[0][1][0], w0b.y, hB.x);
                fma2(acc[0][1][1], w0b.x, hA.y); fma2(acc[0][1][1], w0b.y, hB.y);
                ulonglong2 w1a = *(const ulonglong2*)(pw10 + (t << 2));
                ulonglong2 w1b = *(const ulonglong2*)(pw11 + (t << 2));
                fma2(acc[1][0][0], w1a.x, hA.x); fma2(acc[1][0][0], w1a.y, hB.x);
                fma2(acc[1][0][1], w1a.x, hA.y); fma2(acc[1][0][1], w1a.y, hB.y);
                fma2(acc[1][1][0], w1b.x, hA.x); fma2(acc[1][1][0], w1b.y, hB.x);
                fma2(acc[1][1][1], w1b.x, hA.y); fma2(acc[1][1][1], w1b.y, hB.y);
                ulonglong2 w2a = *(const ulonglong2*)(pw20 + (t << 2));
                ulonglong2 w2b = *(const ulonglong2*)(pw21 + (t << 2));
                fma2(acc[2][0][0], w2a.x, hA.x); fma2(acc[2][0][0], w2a.y, hB.x);
                fma2(acc[2][0][1], w2a.x, hA.y); fma2(acc[2][0][1], w2a.y, hB.y);
                fma2(acc[2][1][0], w2b.x, hA.x); fma2(acc[2][1][0], w2b.y, hB.x);
                fma2(acc[2][1][1], w2b.x, hA.y); fma2(acc[2][1][1], w2b.y, hB.y);
            }
            __syncthreads();   // all warps done with buffer j%3
            if (j < 5 && tid == 0) {
                int jj = j + 3;
                int cs2 = (jj + ic) & 7;
                mb_tx(mb0 + jj * 8, 32768u);
                bulkcp(hst_s + (unsigned)((jj % 3) * 32768), hin + (size_t)cs2 * 8192,
                       32768u, mb0 + jj * 8);
            }
        }

        // re-init mbarriers for next step (all copies consumed, all threads
        // past their waits thanks to the final __syncthreads above)
        if (tid < 8) {
            mb_inval(mb0 + tid * 8);
            mb_init(mb0 + tid * 8);
        }

        // --- epilogue: fold partials, gates, store h(t+1) + ys ---
        float sG[3][2][2];
#pragma unroll
        for (int g = 0; g < 3; g++)
#pragma unroll
            for (int ii = 0; ii < 2; ii++)
#pragma unroll
                for (int bs = 0; bs < 2; bs++) {
                    float2 a = *(float2*)&acc[g][ii][bs];
                    sG[g][ii][bs] = a.x + a.y;
                }
        float bR[2] = { bR0, bR1 }, bZ[2] = { bZ0, bZ1 }, bN[2] = { bN0, bN1 };
        float holdv[2][2] = { { hold4.x, hold4.z }, { hold4.y, hold4.w } };
        bool msk[2] = { step < len0, step < len1 };
        float ho[2][2], yv[2][2];
#pragma unroll
        for (int ii = 0; ii < 2; ii++) {
#pragma unroll
            for (int bs = 0; bs < 2; bs++) {
                float xr = ii ? xg[0][bs].y : xg[0][bs].x;
                float xz = ii ? xg[1][bs].y : xg[1][bs].x;
                float xn = ii ? xg[2][bs].y : xg[2][bs].x;
                float hold = holdv[ii][bs];
                float rg = sigf(xr + sG[0][ii][bs] + bR[ii]);
                float zg = sigf(xz + sG[1][ii][bs] + bZ[ii]);
                float ng = tanhf(xn + rg * (sG[2][ii][bs] + bN[ii]));
                float hn = (1.f - zg) * ng + zg * hold;
                ho[ii][bs] = msk[bs] ? hn : hold;
                yv[ii][bs] = msk[bs] ? hn : 0.f;
            }
        }
        *(float4*)&hout[(size_t)(i_a >> 1) * 256 + b0 * 2] =
            make_float4(ho[0][0], ho[1][0], ho[0][1], ho[1][1]);
#pragma unroll
        for (int ii = 0; ii < 2; ii++)
            *(float2*)&g_ys[(((size_t)d * nS + step) * nH + i_a + ii) * nB + b0] =
                make_float2(yv[ii][0], yv[ii][1]);

        dir_barrier(d, base + 2 + step);
    }
}

// ============================================================
// 4) Output head (unchanged)
// ============================================================
__global__ void __launch_bounds__(256) out_kernel(
    const float* __restrict__ Wlin, const float* __restrict__ blin,
    const int* __restrict__ lengths, float* __restrict__ out) {
    __shared__ float As[64][64];
    __shared__ float Ws[64][65];
    __shared__ int lensm[64];
    int bh = blockIdx.x, s = blockIdx.y;
    int tid = threadIdx.x;
    if (tid < 64) lensm[tid] = lengths[bh * 64 + tid];
    int l = tid & 63, bg = tid >> 6;
    float acc[16];
#pragma unroll
    for (int j = 0; j < 16; j++) acc[j] = 0.f;

    for (int kc = 0; kc < 1024; kc += 64) {
        __syncthreads();
        if (kc < 512) {
            for (int p = tid; p < 1024; p += 256) {
                int kk = p >> 4, b4 = (p & 15) * 4;
                *(float4*)&As[kk][b4] = *(const float4*)
                    &g_ys[(((size_t)0 * nS + s) * nH + kc + kk) * nB + bh * 64 + b4];
            }
        } else {
            for (int p = tid; p < 4096; p += 256) {
                int kk = p >> 6, bb = p & 63;
                int b = bh * 64 + bb, len = lensm[bb];
                float v = 0.f;
                if (s < len) {
                    int t = len - 1 - s;
                    v = g_ys[(((size_t)1 * nS + t) * nH + (kc - 512 + kk)) * nB + b];
                }
                As[kk][bb] = v;
            }
        }
        for (int p = tid; p < 1024; p += 256) {
            int ll = p >> 4, k = (p & 15) * 4;
            float4 v = *(const float4*)&Wlin[(size_t)ll * 1024 + kc + k];
            Ws[k + 0][ll] = v.x; Ws[k + 1][ll] = v.y;
            Ws[k + 2][ll] = v.z; Ws[k + 3][ll] = v.w;
        }
        __syncthreads();
#pragma unroll 8
        for (int kk = 0; kk < 64; kk++) {
            float wv = Ws[kk][l];
            float4 h0 = *(float4*)&As[kk][bg * 16 + 0];
            float4 h1 = *(float4*)&As[kk][bg * 16 + 4];
            float4 h2 = *(float4*)&As[kk][bg * 16 + 8];
            float4 h3 = *(float4*)&As[kk][bg * 16 + 12];
            acc[0] += h0.x * wv; acc[1] += h0.y * wv; acc[2] += h0.z * wv; acc[3] += h0.w * wv;
            acc[4] += h1.x * wv; acc[5] += h1.y * wv; acc[6] += h1.z * wv; acc[7] += h1.w * wv;
            acc[8] += h2.x * wv; acc[9] += h2.y * wv; acc[10] += h2.z * wv; acc[11] += h2.w * wv;
            acc[12] += h3.x * wv; acc[13] += h3.y * wv; acc[14] += h3.z * wv; acc[15] += h3.w * wv;
        }
    }
    __syncthreads();
    float bias = blin[l];
#pragma unroll
    for (int j = 0; j < 16; j++) As[bg * 16 + j][l] = acc[j] + bias;
    __syncthreads();
    for (int p = tid; p < 1024; p += 256) {
        int bb = p >> 4, l4 = (p & 15) * 4;
        *(float4*)&out[(size_t)(bh * 64 + bb) * nS * nL + s * nL + l4] =
            *(float4*)&As[bb][l4];
    }
}

// ============================================================
extern "C" void kernel_launch(void* const* d_in, const int* in_sizes, int n_in,
                              void* d_out, int out_size) {
    const int*   chars   = (const int*)d_in[0];
    const int*   lengths = (const int*)d_in[1];
    const float* forget  = (const float*)d_in[2];
    const float* W_ih_f  = (const float*)d_in[3];
    const float* W_hh_f  = (const float*)d_in[4];
    const float* b_ih_f  = (const float*)d_in[5];
    const float* b_hh_f  = (const float*)d_in[6];
    const float* W_ih_b  = (const float*)d_in[7];
    const float* W_hh_b  = (const float*)d_in[8];
    const float* b_ih_b  = (const float*)d_in[9];
    const float* b_hh_b  = (const float*)d_in[10];
    const float* W_lin   = (const float*)d_in[11];
    const float* b_lin   = (const float*)d_in[12];
    float* out = (float*)d_out;

    cudaFuncSetAttribute(xwk, cudaFuncAttributeMaxDynamicSharedMemorySize, 90 * 1024);
    cudaFuncSetAttribute(scan_kernel, cudaFuncAttributeMaxDynamicSharedMemorySize, 152 * 1024);

    wt_kernel<<<(2 * nV * nG + 255) / 256, 256>>>(W_ih_f, W_ih_b);
    xwk<<<dim3(12, 128, 2), 256, 82000>>>(chars, forget, b_ih_f, b_ih_b);
    noop_kernel<<<1, 32>>>();   // keeps ncu capture slot on scan_kernel
    scan_kernel<<<NBLK, 256, 148600>>>(W_hh_f, b_hh_f, W_hh_b, b_hh_b, lengths);
    out_kernel<<<dim3(2, 128), 256>>>(W_lin, b_lin, lengths, out);
}

// round 12
// speedup vs baseline: 1.2075x; 1.1466x over previous
#include <cuda_runtime.h>
#include <math.h>

typedef unsigned long long ull;

// Problem dims
constexpr int nB = 128;
constexpr int nS = 128;
constexpr int nV = 128;
constexpr int nH = 512;
constexpr int nL = 64;
constexpr int nG = 3 * nH;     // 1536
constexpr int NBLK = 128;      // persistent scan blocks (<= 148 SMs)

// ---- scratch (device globals; no allocations allowed) ----
__device__ float g_WT[2][nV * nG];            // W_ih transposed [d][v][g]
__device__ float g_xw[2ull * nS * nB * nG];   // [d][s][b][g]
__device__ float g_ys[2ull * nS * nH * nB];   // [d][s][i][b]  (zero-init; frozen entries never written)
// h double buffer, interleaved: [parity][d][k2][b][2]
__device__ float g_h[2][2][nH * nB];
__device__ unsigned g_cnt2[64];               // per-direction arrivals (idx d*32)
__device__ unsigned g_gen2[64];               // per-direction generation (idx d*32)

// ============================================================
// helpers
// ============================================================
__device__ __forceinline__ void fma2(ull& d, ull a, ull b) {
    asm("fma.rn.f32x2 %0, %1, %2, %0;" : "+l"(d) : "l"(a), "l"(b));
}
__device__ __forceinline__ void cpa16(unsigned dst, const void* src) {
    asm volatile("cp.async.cg.shared.global [%0], [%1], 16;" :: "r"(dst), "l"(src));
}
__device__ __forceinline__ void cpa_commit() {
    asm volatile("cp.async.commit_group;");
}
template <int N>
__device__ __forceinline__ void cpa_wait() {
    asm volatile("cp.async.wait_group %0;" :: "n"(N));
}
__device__ __forceinline__ float sigf(float x) {
    return 1.f / (1.f + expf(-x));
}

// per-direction sense barrier across 64 co-resident blocks
__device__ __forceinline__ void dir_barrier(int d, unsigned target) {
    __threadfence();
    __syncthreads();
    if (threadIdx.x == 0) {
        unsigned* cnt = &g_cnt2[d * 32];
        unsigned* gen = &g_gen2[d * 32];
        unsigned t = atomicAdd(cnt, 1);
        if (t == 63) {
            *cnt = 0;
            __threadfence();
            atomicExch(gen, target);
        } else {
            unsigned v;
            do {
                asm volatile("ld.volatile.global.u32 %0, [%1];" : "=r"(v) : "l"(gen));
            } while (v != target);
            __threadfence();
        }
    }
    __syncthreads();
}

// ============================================================
// 1) Transpose W_ih (g,v) -> (v,g)
// ============================================================
__global__ void wt_kernel(const float* __restrict__ Wf,
                          const float* __restrict__ Wb) {
    int idx = blockIdx.x * 256 + threadIdx.x;
    if (idx >= 2 * nV * nG) return;
    int d = idx / (nV * nG);
    int rem = idx - d * (nV * nG);
    int v = rem / nG, g = rem - v * nG;
    const float* Wsrc = d ? Wb : Wf;
    g_WT[d][rem] = Wsrc[g * nV + v];
}

// ============================================================
// noop: keeps ncu's profiled launch slot on scan_kernel
// ============================================================
__global__ void noop_kernel() {}

// ============================================================
// 2) Sparse input projection straight from chars (<=16 nnz per row)
// ============================================================
__global__ void __launch_bounds__(256) xwk(const int* __restrict__ chars,
                                           const float* __restrict__ forget,
                                           const float* __restrict__ bihf,
                                           const float* __restrict__ bihb) {
    extern __shared__ float sm[];
    float* Wv  = sm;                       // [128 v][128 g]
    float* swt = sm + 16384;               // [128 b][16]
    int*   sc  = (int*)(sm + 18432);       // [128 b][16]
    float* fp  = sm + 20480;               // forget powers [17]

    int gc = blockIdx.x, s = blockIdx.y, d = blockIdx.z;
    int tid = threadIdx.x;

    const float* WT = g_WT[d];
    for (int p = tid; p < 4096; p += 256) {
        int v = p >> 5, g4 = p & 31;
        *(float4*)&Wv[v * 128 + g4 * 4] =
            *(const float4*)&WT[(size_t)v * nG + gc * 128 + g4 * 4];
    }
    if (tid == 0) {
        float f = *forget;
        fp[0] = 1.f;
        for (int i = 1; i <= 16; i++) fp[i] = fp[i - 1] * f;
    }
    __syncthreads();
    if (tid < 128) {
        int b = tid;
        const int* cp = chars + ((size_t)b * nS + s) * 16;
        int c[16];
#pragma unroll
        for (int w = 0; w < 16; w++) c[w] = cp[w];
        int cnt = 0;
#pragma unroll
        for (int w = 15; w >= 0; w--) {
            bool nz = (c[w] != 0);
            swt[b * 16 + w] = nz ? fp[cnt] : 0.f;
            sc[b * 16 + w] = c[w];
            cnt += nz ? 1 : 0;
        }
    }
    __syncthreads();

    int gq = tid & 31, rp = tid >> 5;
    const float* bih = d ? bihb : bihf;
    float4 bias = *(const float4*)&bih[gc * 128 + gq * 4];
    for (int it = 0; it < 16; it++) {
        int b = it * 8 + rp;
        float a0 = bias.x, a1 = bias.y, a2 = bias.z, a3 = bias.w;
#pragma unroll
        for (int w = 0; w < 16; w++) {
            float ww = swt[b * 16 + w];
            int cc = sc[b * 16 + w];
            float4 wv = *(const float4*)&Wv[cc * 128 + gq * 4];
            a0 += ww * wv.x; a1 += ww * wv.y; a2 += ww * wv.z; a3 += ww * wv.w;
        }
        *(float4*)&g_xw[(((size_t)d * nS + s) * nB + b) * nG + gc * 128 + gq * 4] =
            make_float4(a0, a1, a2, a3);
    }
}

// ============================================================
// 3) Persistent bidirectional GRU scan with LENGTH-BASED SKIPPING.
//    128 blocks: d = blk>>6, i-chunk of 8 = blk&63.
//    Warp w: hw = w>>2 (32-batch offset), row pair r0 = 2*(w&3).
//    Lane slots: slot0 = batch hw*32+lane, slot1 = batch 64+hw*32+lane.
//    lengths sorted descending -> a slot's whole 32-batch group freezes
//    together: slot active iff step <= lensm[group_base] (+1 grace step
//    keeps both h parity buffers final). Frozen slots skip FMA, epilogue
//    and staged columns (active batches are a contiguous prefix).
// ============================================================
__global__ void __launch_bounds__(256, 1) scan_kernel(
    const float* __restrict__ Whf, const float* __restrict__ bhf,
    const float* __restrict__ Whb, const float* __restrict__ bhb,
    const int* __restrict__ lengths) {
    extern __shared__ float sm[];
    float* Wsm = sm;                     // [24 rows][512 k] (48 KB)
    float* hst = sm + 12288;             // 2 x [32 k2][128 b][2] (64 KB)
    int*   lensm = (int*)(sm + 28672);   // [128]
    unsigned* sbase = (unsigned*)(sm + 28800);

    int tid = threadIdx.x;
    int d = blockIdx.x >> 6, ic = blockIdx.x & 63, i0 = ic * 8;
    const float* Wh = d ? Whb : Whf;
    const float* bh_p = d ? bhb : bhf;

    // load 24 W rows (3 gates x 8 i) once, natural layout
    for (int p = tid; p < 3072; p += 256) {
        int row = p >> 7, q = p & 127;
        float4 v = *(const float4*)&Wh[((size_t)(row >> 3) * nH + i0 + (row & 7)) * nH + q * 4];
        *(float4*)&Wsm[row * 512 + q * 4] = v;
    }
    if (tid < 128) lensm[tid] = lengths[tid];
    if (tid == 0) {
        unsigned v;
        asm volatile("ld.volatile.global.u32 %0, [%1];" : "=r"(v) : "l"(&g_gen2[d * 32]));
        *sbase = v;
    }
    // zero initial hidden state (parity 0), this block's k2 slice
    for (int p = tid; p < 1024; p += 256)
        g_h[0][d][(size_t)(i0 >> 1) * 256 + p] = 0.f;
    __syncthreads();
    unsigned base = *sbase;
    // group-base lengths for staging prefix
    int l32 = lensm[32], l64 = lensm[64], l96 = lensm[96];
    dir_barrier(d, base + 1);

    int w = tid >> 5, lane = tid & 31;
    int hw = w >> 2;                      // 32-batch offset selector
    int r0 = (w & 3) * 2;
    int b_s0 = hw * 32 + lane;            // slot0 batch
    int b_s1 = b_s0 + 64;                 // slot1 batch
    int i_a = i0 + r0, i_b = i_a + 1;
    int i2 = i_a >> 1;
    float bR0 = bh_p[i_a], bR1 = bh_p[i_b];
    float bZ0 = bh_p[nH + i_a], bZ1 = bh_p[nH + i_b];
    float bN0 = bh_p[2 * nH + i_a], bN1 = bh_p[2 * nH + i_b];
    unsigned hst_s = (unsigned)__cvta_generic_to_shared(hst);
    int len_s0 = lensm[b_s0], len_s1 = lensm[b_s1];
    int lbase0 = lensm[hw * 32];          // slot0 group base len
    int lbase1 = lensm[64 + hw * 32];     // slot1 group base len

    // per-warp weight row base pointers [gate][ii]
    const float* wp[3][2];
#pragma unroll
    for (int g = 0; g < 3; g++)
#pragma unroll
        for (int ii = 0; ii < 2; ii++)
            wp[g][ii] = Wsm + ((g * 8 + r0 + ii) << 9);

    for (int step = 0; step < nS; step++) {
        int par = step & 1;
        const float* hin = g_h[par][d];
        float* hout = g_h[par ^ 1][d];
        bool act0 = step <= lbase0;       // slot0 live (incl. grace)
        bool act1 = step <= lbase1;       // slot1 live
        // staged column prefix: number of active 32-batch groups
        int ng = 1 + (step <= l32 ? 1 : 0) + (step <= l64 ? 1 : 0)
                   + (step <= l96 ? 1 : 0);
        int seglim = ng << 4;             // seg < 16*ng  (seg covers 2 batches)

        // --- epilogue inputs: per-slot early LDG (hidden under k-loop) ---
        float2 xg0[3], xg1[3], hold0, hold1;
        if (act0) {
            int seff = d ? ((len_s0 - 1 - step) > 0 ? (len_s0 - 1 - step) : 0) : step;
            const float* bp = &g_xw[(((size_t)d * nS + seff) * nB + b_s0) * nG + i_a];
            xg0[0] = __ldcg((const float2*)bp);
            xg0[1] = __ldcg((const float2*)(bp + nH));
            xg0[2] = __ldcg((const float2*)(bp + 2 * nH));
            hold0 = __ldcg((const float2*)&hin[(size_t)i2 * 256 + b_s0 * 2]);
        }
        if (act1) {
            int seff = d ? ((len_s1 - 1 - step) > 0 ? (len_s1 - 1 - step) : 0) : step;
            const float* bp = &g_xw[(((size_t)d * nS + seff) * nB + b_s1) * nG + i_a];
            xg1[0] = __ldcg((const float2*)bp);
            xg1[1] = __ldcg((const float2*)(bp + nH));
            xg1[2] = __ldcg((const float2*)(bp + 2 * nH));
            hold1 = __ldcg((const float2*)&hin[(size_t)i2 * 256 + b_s1 * 2]);
        }

        // --- stage chunk 0 (active-prefix columns only) ---
#pragma unroll
        for (int q = 0; q < 8; q++) {
            int p = tid + q * 256;
            int k2 = p >> 6, seg = p & 63;
            if (seg < seglim)
                cpa16(hst_s + (unsigned)((k2 * 256 + seg * 4) * 4),
                      hin + (size_t)k2 * 256 + seg * 4);
        }
        cpa_commit();

        // acc[g][ii][slot]: f32x2 (even-k, odd-k) partials
        ull acc[3][2][2];
#pragma unroll
        for (int g = 0; g < 3; g++)
#pragma unroll
            for (int ii = 0; ii < 2; ii++)
#pragma unroll
                for (int bs = 0; bs < 2; bs++) acc[g][ii][bs] = 0ull;

        for (int c = 0; c < 8; c++) {
            if (c < 7) {
                const float* src = hin + (size_t)(c + 1) * 8192;
                unsigned dst = hst_s + (unsigned)((((c + 1) & 1) * 8192) * 4);
#pragma unroll
                for (int q = 0; q < 8; q++) {
                    int p = tid + q * 256;
                    int k2 = p >> 6, seg = p & 63;
                    if (seg < seglim)
                        cpa16(dst + (unsigned)((k2 * 256 + seg * 4) * 4),
                              src + (size_t)k2 * 256 + seg * 4);
                }
                cpa_commit();
                cpa_wait<1>();
            } else {
                cpa_wait<0>();
            }
            __syncthreads();

            const float* hb = hst + (c & 1) * 8192 + b_s0 * 2;
            const float* pw00 = wp[0][0] + c * 64; const float* pw01 = wp[0][1] + c * 64;
            const float* pw10 = wp[1][0] + c * 64; const float* pw11 = wp[1][1] + c * 64;
            const float* pw20 = wp[2][0] + c * 64; const float* pw21 = wp[2][1] + c * 64;
            if (act1) {
                // full: both slots
#pragma unroll
                for (int t = 0; t < 16; t++) {
                    const float* hrow = hb + (t << 9);
                    ull hA0 = *(const ull*)(hrow);
                    ull hB0 = *(const ull*)(hrow + 256);
                    ull hA1 = *(const ull*)(hrow + 128);
                    ull hB1 = *(const ull*)(hrow + 384);
                    ulonglong2 w0a = *(const ulonglong2*)(pw00 + (t << 2));
                    ulonglong2 w0b = *(const ulonglong2*)(pw01 + (t << 2));
                    fma2(acc[0][0][0], w0a.x, hA0); fma2(acc[0][0][0], w0a.y, hB0);
                    fma2(acc[0][0][1], w0a.x, hA1); fma2(acc[0][0][1], w0a.y, hB1);
                    fma2(acc[0][1][0], w0b.x, hA0); fma2(acc[0][1][0], w0b.y, hB0);
                    fma2(acc[0][1][1], w0b.x, hA1); fma2(acc[0][1][1], w0b.y, hB1);
                    ulonglong2 w1a = *(const ulonglong2*)(pw10 + (t << 2));
                    ulonglong2 w1b = *(const ulonglong2*)(pw11 + (t << 2));
                    fma2(acc[1][0][0], w1a.x, hA0); fma2(acc[1][0][0], w1a.y, hB0);
                    fma2(acc[1][0][1], w1a.x, hA1); fma2(acc[1][0][1], w1a.y, hB1);
                    fma2(acc[1][1][0], w1b.x, hA0); fma2(acc[1][1][0], w1b.y, hB0);
                    fma2(acc[1][1][1], w1b.x, hA1); fma2(acc[1][1][1], w1b.y, hB1);
                    ulonglong2 w2a = *(const ulonglong2*)(pw20 + (t << 2));
                    ulonglong2 w2b = *(const ulonglong2*)(pw21 + (t << 2));
                    fma2(acc[2][0][0], w2a.x, hA0); fma2(acc[2][0][0], w2a.y, hB0);
                    fma2(acc[2][0][1], w2a.x, hA1); fma2(acc[2][0][1], w2a.y, hB1);
                    fma2(acc[2][1][0], w2b.x, hA0); fma2(acc[2][1][0], w2b.y, hB0);
                    fma2(acc[2][1][1], w2b.x, hA1); fma2(acc[2][1][1], w2b.y, hB1);
                }
            } else if (act0) {
                // half: slot0 only
#pragma unroll
                for (int t = 0; t < 16; t++) {
                    const float* hrow = hb + (t << 9);
                    ull hA0 = *(const ull*)(hrow);
                    ull hB0 = *(const ull*)(hrow + 256);
                    ulonglong2 w0a = *(const ulonglong2*)(pw00 + (t << 2));
                    ulonglong2 w0b = *(const ulonglong2*)(pw01 + (t << 2));
                    fma2(acc[0][0][0], w0a.x, hA0); fma2(acc[0][0][0], w0a.y, hB0);
                    fma2(acc[0][1][0], w0b.x, hA0); fma2(acc[0][1][0], w0b.y, hB0);
                    ulonglong2 w1a = *(const ulonglong2*)(pw10 + (t << 2));
                    ulonglong2 w1b = *(const ulonglong2*)(pw11 + (t << 2));
                    fma2(acc[1][0][0], w1a.x, hA0); fma2(acc[1][0][0], w1a.y, hB0);
                    fma2(acc[1][1][0], w1b.x, hA0); fma2(acc[1][1][0], w1b.y, hB0);
                    ulonglong2 w2a = *(const ulonglong2*)(pw20 + (t << 2));
                    ulonglong2 w2b = *(const ulonglong2*)(pw21 + (t << 2));
                    fma2(acc[2][0][0], w2a.x, hA0); fma2(acc[2][0][0], w2a.y, hB0);
                    fma2(acc[2][1][0], w2b.x, hA0); fma2(acc[2][1][0], w2b.y, hB0);
                }
            }
            __syncthreads();
        }

        // --- epilogue per slot: fold partials, gates, store h(t+1) + ys ---
        float bR[2] = { bR0, bR1 }, bZ[2] = { bZ0, bZ1 }, bN[2] = { bN0, bN1 };
#pragma unroll
        for (int s = 0; s < 2; s++) {
            bool act = s ? act1 : act0;
            if (!act) continue;
            int b = s ? b_s1 : b_s0;
            int len = s ? len_s1 : len_s0;
            float2* xg = s ? xg1 : xg0;
            float2 hold = s ? hold1 : hold0;
            bool m = step < len;
            float ho[2], yv[2];
#pragma unroll
            for (int ii = 0; ii < 2; ii++) {
                float2 a = *(float2*)&acc[0][ii][s]; float sR = a.x + a.y;
                float2 z = *(float2*)&acc[1][ii][s]; float sZ = z.x + z.y;
                float2 n = *(float2*)&acc[2][ii][s]; float sN = n.x + n.y;
                float xr = ii ? xg[0].y : xg[0].x;
                float xz = ii ? xg[1].y : xg[1].x;
                float xn = ii ? xg[2].y : xg[2].x;
                float hd = ii ? hold.y : hold.x;
                float rg = sigf(xr + sR + bR[ii]);
                float zg = sigf(xz + sZ + bZ[ii]);
                float ngg = tanhf(xn + rg * (sN + bN[ii]));
                float hn = (1.f - zg) * ngg + zg * hd;
                ho[ii] = m ? hn : hd;
                yv[ii] = m ? hn : 0.f;
            }
            *(float2*)&hout[(size_t)i2 * 256 + b * 2] = make_float2(ho[0], ho[1]);
            g_ys[(((size_t)d * nS + step) * nH + i_a) * nB + b] = yv[0];
            g_ys[(((size_t)d * nS + step) * nH + i_b) * nB + b] = yv[1];
        }

        dir_barrier(d, base + 2 + step);
    }
}

// ============================================================
// 4) Output head (unchanged)
// ============================================================
__global__ void __launch_bounds__(256) out_kernel(
    const float* __restrict__ Wlin, const float* __restrict__ blin,
    const int* __restrict__ lengths, float* __restrict__ out) {
    __shared__ float As[64][64];
    __shared__ float Ws[64][65];
    __shared__ int lensm[64];
    int bh = blockIdx.x, s = blockIdx.y;
    int tid = threadIdx.x;
    if (tid < 64) lensm[tid] = lengths[bh * 64 + tid];
    int l = tid & 63, bg = tid >> 6;
    float acc[16];
#pragma unroll
    for (int j = 0; j < 16; j++) acc[j] = 0.f;

    for (int kc = 0; kc < 1024; kc += 64) {
        __syncthreads();
        if (kc < 512) {
            for (int p = tid; p < 1024; p += 256) {
                int kk = p >> 4, b4 = (p & 15) * 4;
                *(float4*)&As[kk][b4] = *(const float4*)
                    &g_ys[(((size_t)0 * nS + s) * nH + kc + kk) * nB + bh * 64 + b4];
            }
        } else {
            for (int p = tid; p < 4096; p += 256) {
                int kk = p >> 6, bb = p & 63;
                int b = bh * 64 + bb, len = lensm[bb];
                float v = 0.f;
                if (s < len) {
                    int t = len - 1 - s;
                    v = g_ys[(((size_t)1 * nS + t) * nH + (kc - 512 + kk)) * nB + b];
                }
                As[kk][bb] = v;
            }
        }
        for (int p = tid; p < 1024; p += 256) {
            int ll = p >> 4, k = (p & 15) * 4;
            float4 v = *(const float4*)&Wlin[(size_t)ll * 1024 + kc + k];
            Ws[k + 0][ll] = v.x; Ws[k + 1][ll] = v.y;
            Ws[k + 2][ll] = v.z; Ws[k + 3][ll] = v.w;
        }
        __syncthreads();
#pragma unroll 8
        for (int kk = 0; kk < 64; kk++) {
            float wv = Ws[kk][l];
            float4 h0 = *(float4*)&As[kk][bg * 16 + 0];
            float4 h1 = *(float4*)&As[kk][bg * 16 + 4];
            float4 h2 = *(float4*)&As[kk][bg * 16 + 8];
            float4 h3 = *(float4*)&As[kk][bg * 16 + 12];
            acc[0] += h0.x * wv; acc[1] += h0.y * wv; acc[2] += h0.z * wv; acc[3] += h0.w * wv;
            acc[4] += h1.x * wv; acc[5] += h1.y * wv; acc[6] += h1.z * wv; acc[7] += h1.w * wv;
            acc[8] += h2.x * wv; acc[9] += h2.y * wv; acc[10] += h2.z * wv; acc[11] += h2.w * wv;
            acc[12] += h3.x * wv; acc[13] += h3.y * wv; acc[14] += h3.z * wv; acc[15] += h3.w * wv;
        }
    }
    __syncthreads();
    float bias = blin[l];
#pragma unroll
    for (int j = 0; j < 16; j++) As[bg * 16 + j][l] = acc[j] + bias;
    __syncthreads();
    for (int p = tid; p < 1024; p += 256) {
        int bb = p >> 4, l4 = (p & 15) * 4;
        *(float4*)&out[(size_t)(bh * 64 + bb) * nS * nL + s * nL + l4] =
            *(float4*)&As[bb][l4];
    }
}

// ============================================================
extern "C" void kernel_launch(void* const* d_in, const int* in_sizes, int n_in,
                              void* d_out, int out_size) {
    const int*   chars   = (const int*)d_in[0];
    const int*   lengths = (const int*)d_in[1];
    const float* forget  = (const float*)d_in[2];
    const float* W_ih_f  = (const float*)d_in[3];
    const float* W_hh_f  = (const float*)d_in[4];
    const float* b_ih_f  = (const float*)d_in[5];
    const float* b_hh_f  = (const float*)d_in[6];
    const float* W_ih_b  = (const float*)d_in[7];
    const float* W_hh_b  = (const float*)d_in[8];
    const float* b_ih_b  = (const float*)d_in[9];
    const float* b_hh_b  = (const float*)d_in[10];
    const float* W_lin   = (const float*)d_in[11];
    const float* b_lin   = (const float*)d_in[12];
    float* out = (float*)d_out;

    cudaFuncSetAttribute(xwk, cudaFuncAttributeMaxDynamicSharedMemorySize, 90 * 1024);
    cudaFuncSetAttribute(scan_kernel, cudaFuncAttributeMaxDynamicSharedMemorySize, 120 * 1024);

    wt_kernel<<<(2 * nV * nG + 255) / 256, 256>>>(W_ih_f, W_ih_b);
    xwk<<<dim3(12, 128, 2), 256, 82000>>>(chars, forget, b_ih_f, b_ih_b);
    noop_kernel<<<1, 32>>>();   // keeps ncu capture slot on scan_kernel
    scan_kernel<<<NBLK, 256, 118000>>>(W_hh_f, b_hh_f, W_hh_b, b_hh_b, lengths);
    out_kernel<<<dim3(2, 128), 256>>>(W_lin, b_lin, lengths, out);
}